// round 6
// baseline (speedup 1.0000x reference)
#include <cuda_runtime.h>
#include <math.h>

#define NN 50000
#define EE 400000
#define FF 128
#define TF 384
typedef unsigned long long ull;

// ---------------- packed f32x2 helpers ----------------
__device__ __forceinline__ ull pk2(float x, float y) {
    ull r; asm("mov.b64 %0,{%1,%2};" : "=l"(r) : "f"(x), "f"(y)); return r;
}
__device__ __forceinline__ void upk2(ull p, float& x, float& y) {
    asm("mov.b64 {%0,%1},%2;" : "=f"(x), "=f"(y) : "l"(p));
}
__device__ __forceinline__ ull ffma2(ull a, ull b, ull c) {
    ull d; asm("fma.rn.f32x2 %0,%1,%2,%3;" : "=l"(d) : "l"(a), "l"(b), "l"(c)); return d;
}

// ---------------- device scratch ----------------
__device__ float g_phi[NN * TF];
__device__ float g_hid[NN * FF];      // MLP hidden
__device__ float g_h[NN * 256];       // [:128]=s_msg, [128:256]=Vn
__device__ float g_v[NN * TF];        // [n][c][f] rows of M=3N
__device__ float g_U[NN * TF];
__device__ float g_V[NN * TF];
__device__ float g_a[NN * TF];
__device__ float g_erbf[EE * 24];
__device__ float g_WwT[20 * TF];
__device__ int   g_cnt[NN];
__device__ int   g_off[NN + 1];
__device__ int   g_cur[NN];
__device__ int   g_eid[EE];

// ---------------- CSR build ----------------
__global__ void k_zero_cnt() {
    int i = blockIdx.x * 256 + threadIdx.x;
    if (i < NN) g_cnt[i] = 0;
}
__global__ void k_count(const int* __restrict__ dst) {
    int e = blockIdx.x * 256 + threadIdx.x;
    if (e < EE) atomicAdd(&g_cnt[dst[e]], 1);
}
// one block, 1024 threads: chunked scan, writes g_off and g_cur
__global__ __launch_bounds__(1024) void k_scan() {
    __shared__ int ws[32];
    int tid = threadIdx.x, lane = tid & 31, wid = tid >> 5;
    const int C = 49;                       // 1024*49 >= NN
    int b0 = tid * C, b1 = b0 + C; if (b1 > NN) b1 = NN;
    int sum = 0;
    for (int i = b0; i < b1; i++) sum += g_cnt[i];
    int v = sum;
    #pragma unroll
    for (int d = 1; d < 32; d <<= 1) {
        int y = __shfl_up_sync(0xffffffffu, v, d);
        if (lane >= d) v += y;
    }
    if (lane == 31) ws[wid] = v;
    __syncthreads();
    if (wid == 0) {
        int s = ws[lane];
        #pragma unroll
        for (int d = 1; d < 32; d <<= 1) {
            int y = __shfl_up_sync(0xffffffffu, s, d);
            if (lane >= d) s += y;
        }
        ws[lane] = s;
    }
    __syncthreads();
    int run = v - sum + (wid ? ws[wid - 1] : 0);
    for (int i = b0; i < b1; i++) {
        g_off[i] = run; g_cur[i] = run;
        run += g_cnt[i];
    }
    if (tid == 0) g_off[NN] = EE;
}
__global__ void k_scatter(const int* __restrict__ dst) {
    int e = blockIdx.x * 256 + threadIdx.x;
    if (e < EE) {
        int p = atomicAdd(&g_cur[dst[e]], 1);
        g_eid[p] = e;
    }
}
__global__ void k_wwt(const float* __restrict__ Ww) {
    int i = blockIdx.x * 256 + threadIdx.x;
    if (i < TF * 20) {
        int j = i / 20, k = i % 20;
        g_WwT[k * TF + j] = Ww[i];
    }
}

// ---------------- per-edge dir + rbf ----------------
__global__ void k_edge(const float* __restrict__ pos, const int* __restrict__ src,
                       const int* __restrict__ dst) {
    int e = blockIdx.x * 256 + threadIdx.x;
    if (e >= EE) return;
    int s = src[e], d = dst[e];
    float rx = pos[d * 3 + 0] - pos[s * 3 + 0];
    float ry = pos[d * 3 + 1] - pos[s * 3 + 1];
    float rz = pos[d * 3 + 2] - pos[s * 3 + 2];
    float dist = sqrtf(rx * rx + ry * ry + rz * rz);
    dist = fmaxf(dist, 1e-9f);
    float inv = 1.0f / dist;
    float buf[24];
    buf[0] = rx * inv; buf[1] = ry * inv; buf[2] = rz * inv;
    float c = 3.14159265358979f * dist * 0.2f;
    float sc, cc; sincosf(c, &sc, &cc);
    float sn = sc, cn = cc;
    buf[3] = sn * inv;
    #pragma unroll
    for (int k = 1; k < 20; k++) {
        float sn2 = fmaf(sn, cc, cn * sc);
        float cn2 = fmaf(cn, cc, -sn * sc);
        sn = sn2; cn = cn2;
        buf[3 + k] = sn * inv;
    }
    buf[23] = 0.0f;
    float4* o = (float4*)(g_erbf + (size_t)e * 24);
    #pragma unroll
    for (int q = 0; q < 6; q++) o[q] = ((float4*)buf)[q];
}

// ---------------- gather accumulation (CSR, prefetched) ----------------
__global__ void __launch_bounds__(128) k_gather(const int* __restrict__ src,
                                                const float* __restrict__ bw,
                                                const float* __restrict__ emb,
                                                const int* __restrict__ z) {
    int t = threadIdx.x;
    float w0[20], w2[20];
    #pragma unroll
    for (int k = 0; k < 20; k++) {
        w0[k] = g_WwT[k * TF + t];
        w2[k] = g_WwT[k * TF + 256 + t];
    }
    float b0 = bw[t], b2 = bw[256 + t];
    int nbase = blockIdx.x * 32;
    for (int ii = 0; ii < 32; ii++) {
        int n = nbase + ii;
        if (n >= NN) break;
        int e0 = g_off[n], e1 = g_off[n + 1];
        float accs = 0.f, av0 = 0.f, av1 = 0.f, av2 = 0.f;
        int eC = 0, sC = 0;
        if (e0 < e1) { eC = g_eid[e0]; sC = __ldg(&src[eC]); }
        for (int idx = e0; idx < e1; idx++) {
            const float4* eb = (const float4*)(g_erbf + (size_t)eC * 24);
            float4 q0 = eb[0], q1 = eb[1], q2 = eb[2], q3 = eb[3], q4 = eb[4], q5 = eb[5];
            float p0 = g_phi[(size_t)sC * TF + t];
            float p2 = g_phi[(size_t)sC * TF + 256 + t];
            if (idx + 1 < e1) { eC = g_eid[idx + 1]; sC = __ldg(&src[eC]); }
            float r[20];
            r[0] = q0.w;
            r[1] = q1.x; r[2] = q1.y; r[3] = q1.z; r[4] = q1.w;
            r[5] = q2.x; r[6] = q2.y; r[7] = q2.z; r[8] = q2.w;
            r[9] = q3.x; r[10] = q3.y; r[11] = q3.z; r[12] = q3.w;
            r[13] = q4.x; r[14] = q4.y; r[15] = q4.z; r[16] = q4.w;
            r[17] = q5.x; r[18] = q5.y; r[19] = q5.z;
            float wf0 = b0, wf2 = b2;
            #pragma unroll
            for (int k = 0; k < 20; k++) {
                wf0 = fmaf(r[k], w0[k], wf0);
                wf2 = fmaf(r[k], w2[k], wf2);
            }
            float m2 = p2 * wf2;
            accs = fmaf(p0, wf0, accs);
            av0 = fmaf(m2, q0.x, av0);
            av1 = fmaf(m2, q0.y, av1);
            av2 = fmaf(m2, q0.z, av2);
        }
        int zn = z[n];
        g_h[n * 256 + t] = emb[(size_t)zn * 128 + t] + accs;
        g_v[(n * 3 + 0) * FF + t] = av0;
        g_v[(n * 3 + 1) * FF + t] = av1;
        g_v[(n * 3 + 2) * FF + t] = av2;
    }
}

// ---------------- GEMM: out[:,ob*128:+128] = act(A @ W^T + b) ----------------
// 128x128 tile, 256 thr, 8x8 micro (rowpair f32x2), double-buffered, 1 sync/stage.
template <int KIN, bool EMBED, bool SILU, int LDO>
__global__ __launch_bounds__(256) void k_gemm(
    const float* __restrict__ Ain, const int* __restrict__ z,
    const float* __restrict__ W, const float* __restrict__ B,
    float* __restrict__ out)
{
    __shared__ float As[2 * 8 * 136];     // [buf][k][row]
    __shared__ float Wd[2 * 8 * 256];     // [buf][k][2*col] duplicated pairs
    int tid = threadIdx.x;
    int cg = tid & 15, rg = tid >> 4;
    int rowbase = blockIdx.x * 128;
    int ob = blockIdx.y;
    int lrow = tid >> 1, lk4 = (tid & 1) * 4;
    int grow = rowbase + lrow;
    bool rok = grow < NN;
    const float* arow;
    if (EMBED) {
        int zr = rok ? z[grow] : 0;
        arow = Ain + (size_t)zr * 128;
    } else {
        arow = Ain + (size_t)grow * KIN;
    }
    const float* wrow = W + ((size_t)ob * 128 + lrow) * KIN;

    ull acc[4][8];
    #pragma unroll
    for (int i = 0; i < 4; i++)
        #pragma unroll
        for (int j = 0; j < 8; j++) acc[i][j] = 0ull;

    const int NST = KIN / 8;
    float4 av = rok ? *(const float4*)(arow + lk4) : make_float4(0.f, 0.f, 0.f, 0.f);
    float4 wv = *(const float4*)(wrow + lk4);
    #pragma unroll
    for (int i = 0; i < 4; i++) {
        As[(lk4 + i) * 136 + lrow] = ((const float*)&av)[i];
        float w = ((const float*)&wv)[i];
        *(float2*)&Wd[(lk4 + i) * 256 + 2 * lrow] = make_float2(w, w);
    }
    __syncthreads();

    for (int st = 0; st < NST; st++) {
        int buf = st & 1;
        float4 avn, wvn;
        if (st + 1 < NST) {
            avn = rok ? *(const float4*)(arow + (st + 1) * 8 + lk4)
                      : make_float4(0.f, 0.f, 0.f, 0.f);
            wvn = *(const float4*)(wrow + (st + 1) * 8 + lk4);
        }
        const float* Ab = As + buf * 1088;
        const float* Wb = Wd + buf * 2048;
        #pragma unroll
        for (int kk = 0; kk < 8; kk++) {
            const float* ap_ = Ab + kk * 136 + rg * 8;
            ulonglong2 aA = *(const ulonglong2*)ap_;
            ulonglong2 aB = *(const ulonglong2*)(ap_ + 4);
            const float* wp_ = Wb + kk * 256 + cg * 16;
            ulonglong2 w0 = *(const ulonglong2*)wp_;
            ulonglong2 w1 = *(const ulonglong2*)(wp_ + 4);
            ulonglong2 w2 = *(const ulonglong2*)(wp_ + 8);
            ulonglong2 w3 = *(const ulonglong2*)(wp_ + 12);
            ull ap[4] = {aA.x, aA.y, aB.x, aB.y};
            ull wd[8] = {w0.x, w0.y, w1.x, w1.y, w2.x, w2.y, w3.x, w3.y};
            #pragma unroll
            for (int rp = 0; rp < 4; rp++)
                #pragma unroll
                for (int c = 0; c < 8; c++)
                    acc[rp][c] = ffma2(ap[rp], wd[c], acc[rp][c]);
        }
        if (st + 1 < NST) {
            int nb = buf ^ 1;
            #pragma unroll
            for (int i = 0; i < 4; i++) {
                As[nb * 1088 + (lk4 + i) * 136 + lrow] = ((const float*)&avn)[i];
                float w = ((const float*)&wvn)[i];
                *(float2*)&Wd[nb * 2048 + (lk4 + i) * 256 + 2 * lrow] = make_float2(w, w);
            }
        }
        __syncthreads();
    }

    float bb[8];
    #pragma unroll
    for (int j = 0; j < 8; j++) bb[j] = B[ob * 128 + cg * 8 + j];
    #pragma unroll
    for (int rp = 0; rp < 4; rp++) {
        int r0 = rowbase + rg * 8 + 2 * rp;
        float o0[8], o1[8];
        #pragma unroll
        for (int c = 0; c < 8; c++) {
            float x0, x1; upk2(acc[rp][c], x0, x1);
            x0 += bb[c]; x1 += bb[c];
            if (SILU) { x0 = x0 / (1.f + expf(-x0)); x1 = x1 / (1.f + expf(-x1)); }
            o0[c] = x0; o1[c] = x1;
        }
        if (r0 < NN) {
            float* p = out + (size_t)r0 * LDO + ob * 128 + cg * 8;
            *(float4*)p = make_float4(o0[0], o0[1], o0[2], o0[3]);
            *(float4*)(p + 4) = make_float4(o0[4], o0[5], o0[6], o0[7]);
        }
        if (r0 + 1 < NN) {
            float* p = out + (size_t)(r0 + 1) * LDO + ob * 128 + cg * 8;
            *(float4*)p = make_float4(o1[0], o1[1], o1[2], o1[3]);
            *(float4*)(p + 4) = make_float4(o1[4], o1[5], o1[6], o1[7]);
        }
    }
}

// ---------------- dual GEMM U/V: 128 rows x 64 cols (per matrix) per block ----------------
__global__ __launch_bounds__(256) void k_uv(const float* __restrict__ Wu,
                                            const float* __restrict__ bu,
                                            const float* __restrict__ Wv,
                                            const float* __restrict__ bv) {
    const int M = NN * 3;
    __shared__ float As[2 * 8 * 136];
    __shared__ float WdU[2 * 8 * 128];    // 64 cols duplicated
    __shared__ float WdV[2 * 8 * 128];
    int tid = threadIdx.x;
    int cg = tid & 15, rg = tid >> 4;
    int rowbase = blockIdx.x * 128;
    int cb = blockIdx.y;                   // cols cb*64..+63
    int lrow = tid >> 1, lk4 = (tid & 1) * 4;
    int grow = rowbase + lrow;
    bool rok = grow < M;
    const float* arow = g_v + (size_t)grow * 128;
    bool isU = tid < 128;
    int wlo = (tid & 127) >> 1;
    int wk4 = (tid & 1) * 4;
    const float* wrow = (isU ? Wu : Wv) + ((size_t)cb * 64 + wlo) * 128;
    float* wds = isU ? WdU : WdV;

    ull aU[4][4], aV[4][4];
    #pragma unroll
    for (int i = 0; i < 4; i++)
        #pragma unroll
        for (int j = 0; j < 4; j++) { aU[i][j] = 0ull; aV[i][j] = 0ull; }

    const int NST = 16;
    float4 av = rok ? *(const float4*)(arow + lk4) : make_float4(0.f, 0.f, 0.f, 0.f);
    float4 wv = *(const float4*)(wrow + wk4);
    #pragma unroll
    for (int i = 0; i < 4; i++) {
        As[(lk4 + i) * 136 + lrow] = ((const float*)&av)[i];
        float w = ((const float*)&wv)[i];
        *(float2*)&wds[(wk4 + i) * 128 + 2 * wlo] = make_float2(w, w);
    }
    __syncthreads();

    for (int st = 0; st < NST; st++) {
        int buf = st & 1;
        float4 avn, wvn;
        if (st + 1 < NST) {
            avn = rok ? *(const float4*)(arow + (st + 1) * 8 + lk4)
                      : make_float4(0.f, 0.f, 0.f, 0.f);
            wvn = *(const float4*)(wrow + (st + 1) * 8 + wk4);
        }
        const float* Ab = As + buf * 1088;
        const float* Ub = WdU + buf * 1024;
        const float* Vb = WdV + buf * 1024;
        #pragma unroll
        for (int kk = 0; kk < 8; kk++) {
            const float* ap_ = Ab + kk * 136 + rg * 8;
            ulonglong2 aA = *(const ulonglong2*)ap_;
            ulonglong2 aB = *(const ulonglong2*)(ap_ + 4);
            ulonglong2 u0 = *(const ulonglong2*)(Ub + kk * 128 + cg * 8);
            ulonglong2 u1 = *(const ulonglong2*)(Ub + kk * 128 + cg * 8 + 4);
            ulonglong2 v0 = *(const ulonglong2*)(Vb + kk * 128 + cg * 8);
            ulonglong2 v1 = *(const ulonglong2*)(Vb + kk * 128 + cg * 8 + 4);
            ull ap[4] = {aA.x, aA.y, aB.x, aB.y};
            ull wu[4] = {u0.x, u0.y, u1.x, u1.y};
            ull wv_[4] = {v0.x, v0.y, v1.x, v1.y};
            #pragma unroll
            for (int rp = 0; rp < 4; rp++)
                #pragma unroll
                for (int c = 0; c < 4; c++) {
                    aU[rp][c] = ffma2(ap[rp], wu[c], aU[rp][c]);
                    aV[rp][c] = ffma2(ap[rp], wv_[c], aV[rp][c]);
                }
        }
        if (st + 1 < NST) {
            int nb = buf ^ 1;
            #pragma unroll
            for (int i = 0; i < 4; i++) {
                As[nb * 1088 + (lk4 + i) * 136 + lrow] = ((const float*)&avn)[i];
                float w = ((const float*)&wvn)[i];
                *(float2*)&wds[nb * 1024 + (wk4 + i) * 128 + 2 * wlo] = make_float2(w, w);
            }
        }
        __syncthreads();
    }

    float bbu[4], bbv[4];
    #pragma unroll
    for (int j = 0; j < 4; j++) {
        bbu[j] = bu[cb * 64 + cg * 4 + j];
        bbv[j] = bv[cb * 64 + cg * 4 + j];
    }
    #pragma unroll
    for (int rp = 0; rp < 4; rp++) {
        int r0 = rowbase + rg * 8 + 2 * rp;
        float u0[4], u1[4], v0[4], v1[4];
        #pragma unroll
        for (int c = 0; c < 4; c++) {
            float x0, x1;
            upk2(aU[rp][c], x0, x1); u0[c] = x0 + bbu[c]; u1[c] = x1 + bbu[c];
            upk2(aV[rp][c], x0, x1); v0[c] = x0 + bbv[c]; v1[c] = x1 + bbv[c];
        }
        if (r0 < M) {
            *(float4*)&g_U[(size_t)r0 * 128 + cb * 64 + cg * 4] = make_float4(u0[0], u0[1], u0[2], u0[3]);
            *(float4*)&g_V[(size_t)r0 * 128 + cb * 64 + cg * 4] = make_float4(v0[0], v0[1], v0[2], v0[3]);
        }
        if (r0 + 1 < M) {
            *(float4*)&g_U[(size_t)(r0 + 1) * 128 + cb * 64 + cg * 4] = make_float4(u1[0], u1[1], u1[2], u1[3]);
            *(float4*)&g_V[(size_t)(r0 + 1) * 128 + cb * 64 + cg * 4] = make_float4(v1[0], v1[1], v1[2], v1[3]);
        }
    }
}

__global__ void k_vn() {
    int i = blockIdx.x * 256 + threadIdx.x;
    int n = i >> 7, f = i & 127;
    float x = g_V[(n * 3 + 0) * FF + f];
    float y = g_V[(n * 3 + 1) * FF + f];
    float z = g_V[(n * 3 + 2) * FF + f];
    g_h[n * 256 + 128 + f] = sqrtf(x * x + y * y + z * z);
}

__global__ void k_final(float* __restrict__ out) {
    int i = blockIdx.x * 256 + threadIdx.x;
    int n = i >> 7, f = i & 127;
    const float* ga = g_a + (size_t)n * TF;
    float a1 = ga[f], a2 = ga[128 + f], a3 = ga[256 + f];
    float dot = 0.f;
    float vo[3];
    #pragma unroll
    for (int c = 0; c < 3; c++) {
        int idx = (n * 3 + c) * FF + f;
        float Uc = g_U[idx], Vc = g_V[idx];
        dot = fmaf(Uc, Vc, dot);
        vo[c] = g_v[idx] + Uc * a1;
    }
    out[i] = g_h[n * 256 + f] + a2 + dot * a3;
    float* vp = out + (size_t)NN * FF + (size_t)i * 3;
    vp[0] = vo[0]; vp[1] = vo[1]; vp[2] = vo[2];
}

// ---------------- launch ----------------
extern "C" void kernel_launch(void* const* d_in, const int* in_sizes, int n_in,
                              void* d_out, int out_size) {
    const float* pos = (const float*)d_in[0];
    const float* emb = (const float*)d_in[1];
    const float* Wp1 = (const float*)d_in[2];
    const float* bp1 = (const float*)d_in[3];
    const float* Wp2 = (const float*)d_in[4];
    const float* bp2 = (const float*)d_in[5];
    const float* Ww  = (const float*)d_in[6];
    const float* bw  = (const float*)d_in[7];
    const float* Wu  = (const float*)d_in[8];
    const float* bu  = (const float*)d_in[9];
    const float* Wv  = (const float*)d_in[10];
    const float* bv  = (const float*)d_in[11];
    const float* Wu1 = (const float*)d_in[12];
    const float* bu1 = (const float*)d_in[13];
    const float* Wu2 = (const float*)d_in[14];
    const float* bu2 = (const float*)d_in[15];
    const int* z   = (const int*)d_in[16];
    const int* src = (const int*)d_in[17];
    const int* dst = (const int*)d_in[18];
    float* out = (float*)d_out;

    float *p_hid, *p_phi, *p_h, *p_a;
    cudaGetSymbolAddress((void**)&p_hid, g_hid);
    cudaGetSymbolAddress((void**)&p_phi, g_phi);
    cudaGetSymbolAddress((void**)&p_h, g_h);
    cudaGetSymbolAddress((void**)&p_a, g_a);

    const int gridNF = (NN * FF) / 256;
    const int gridE  = (EE + 255) / 256;
    const int gridN  = (NN + 255) / 256;
    const int gridR  = (NN + 127) / 128;         // 391
    const dim3 gUV((NN * 3 + 127) / 128, 2);     // 1172 x 2
    const int gridGather = (NN + 31) / 32;

    // CSR + edge features (independent of MLPs)
    k_zero_cnt<<<gridN, 256>>>();
    k_count<<<gridE, 256>>>(dst);
    k_scan<<<1, 1024>>>();
    k_scatter<<<gridE, 256>>>(dst);
    k_edge<<<gridE, 256>>>(pos, src, dst);
    k_wwt<<<(TF * 20 + 255) / 256, 256>>>(Ww);

    // phi = silu(emb[z]@Wp1^T+b)@Wp2^T+b
    k_gemm<128, true,  true,  128><<<dim3(gridR, 1), 256>>>(emb,  z, Wp1, bp1, p_hid);
    k_gemm<128, false, false, 384><<<dim3(gridR, 3), 256>>>(p_hid, z, Wp2, bp2, p_phi);

    k_gather<<<gridGather, 128>>>(src, bw, emb, z);

    k_uv<<<gUV, 256>>>(Wu, bu, Wv, bv);
    k_vn<<<gridNF, 256>>>();

    // a = silu(h@Wu1^T+b)@Wu2^T+b
    k_gemm<256, false, true,  128><<<dim3(gridR, 1), 256>>>(p_h,  z, Wu1, bu1, p_hid);
    k_gemm<128, false, false, 384><<<dim3(gridR, 3), 256>>>(p_hid, z, Wu2, bu2, p_a);

    k_final<<<gridNF, 256>>>(out);
}

// round 7
// speedup vs baseline: 1.5111x; 1.5111x over previous
#include <cuda_runtime.h>
#include <math.h>

#define NN 50000
#define EE 400000
#define FF 128
#define TF 384
typedef unsigned long long ull;

// ---------------- packed f32x2 helpers ----------------
__device__ __forceinline__ ull pk2(float x, float y) {
    ull r; asm("mov.b64 %0,{%1,%2};" : "=l"(r) : "f"(x), "f"(y)); return r;
}
__device__ __forceinline__ void upk2(ull p, float& x, float& y) {
    asm("mov.b64 {%0,%1},%2;" : "=f"(x), "=f"(y) : "l"(p));
}
__device__ __forceinline__ ull ffma2(ull a, ull b, ull c) {
    ull d; asm("fma.rn.f32x2 %0,%1,%2,%3;" : "=l"(d) : "l"(a), "l"(b), "l"(c)); return d;
}

// ---------------- device scratch (static, no allocation) ----------------
__device__ float g_phi[NN * TF];
__device__ float g_h[NN * 256];       // [:128]=s_msg, [128:256]=Vn
__device__ float g_v[NN * TF];        // [n][c][f] rows of M=3N
__device__ float g_U[NN * TF];
__device__ float g_V[NN * TF];
__device__ float g_a[NN * TF];
__device__ float g_erbf[EE * 24];
__device__ float g_WwT[20 * TF];
__device__ int   g_cnt[NN];
__device__ int   g_off[NN + 1];
__device__ int   g_cur[NN];
__device__ int   g_eid[EE];

// ---------------- CSR build ----------------
__global__ void k_zero_cnt() {
    int i = blockIdx.x * 256 + threadIdx.x;
    if (i < NN) g_cnt[i] = 0;
}
__global__ void k_count(const int* __restrict__ dst) {
    int e = blockIdx.x * 256 + threadIdx.x;
    if (e < EE) atomicAdd(&g_cnt[dst[e]], 1);
}
// one block, 1024 threads: chunked scan, writes g_off AND g_cur
__global__ __launch_bounds__(1024) void k_scan() {
    __shared__ int ws[32];
    int tid = threadIdx.x, lane = tid & 31, wid = tid >> 5;
    const int C = 49;                       // 1024*49 >= NN
    int b0 = tid * C, b1 = b0 + C; if (b1 > NN) b1 = NN;
    int sum = 0;
    for (int i = b0; i < b1; i++) sum += g_cnt[i];
    int v = sum;
    #pragma unroll
    for (int d = 1; d < 32; d <<= 1) {
        int y = __shfl_up_sync(0xffffffffu, v, d);
        if (lane >= d) v += y;
    }
    if (lane == 31) ws[wid] = v;
    __syncthreads();
    if (wid == 0) {
        int s = ws[lane];
        #pragma unroll
        for (int d = 1; d < 32; d <<= 1) {
            int y = __shfl_up_sync(0xffffffffu, s, d);
            if (lane >= d) s += y;
        }
        ws[lane] = s;
    }
    __syncthreads();
    int run = v - sum + (wid ? ws[wid - 1] : 0);
    for (int i = b0; i < b1; i++) {
        g_off[i] = run; g_cur[i] = run;
        run += g_cnt[i];
    }
    if (tid == 0) g_off[NN] = EE;
}
__global__ void k_scatter(const int* __restrict__ dst) {
    int e = blockIdx.x * 256 + threadIdx.x;
    if (e < EE) {
        int p = atomicAdd(&g_cur[dst[e]], 1);
        g_eid[p] = e;
    }
}
__global__ void k_wwt(const float* __restrict__ Ww) {
    int i = blockIdx.x * 256 + threadIdx.x;
    if (i < TF * 20) {
        int j = i / 20, k = i % 20;
        g_WwT[k * TF + j] = Ww[i];
    }
}

// ---------------- per-edge dir + rbf ----------------
__global__ void k_edge(const float* __restrict__ pos, const int* __restrict__ src,
                       const int* __restrict__ dst) {
    int e = blockIdx.x * 256 + threadIdx.x;
    if (e >= EE) return;
    int s = src[e], d = dst[e];
    float rx = pos[d * 3 + 0] - pos[s * 3 + 0];
    float ry = pos[d * 3 + 1] - pos[s * 3 + 1];
    float rz = pos[d * 3 + 2] - pos[s * 3 + 2];
    float dist = sqrtf(rx * rx + ry * ry + rz * rz);
    dist = fmaxf(dist, 1e-9f);
    float inv = 1.0f / dist;
    float buf[24];
    buf[0] = rx * inv; buf[1] = ry * inv; buf[2] = rz * inv;
    float c = 3.14159265358979f * dist * 0.2f;
    float sc, cc; sincosf(c, &sc, &cc);
    float sn = sc, cn = cc;
    buf[3] = sn * inv;
    #pragma unroll
    for (int k = 1; k < 20; k++) {
        float sn2 = fmaf(sn, cc, cn * sc);
        float cn2 = fmaf(cn, cc, -sn * sc);
        sn = sn2; cn = cn2;
        buf[3 + k] = sn * inv;
    }
    buf[23] = 0.0f;
    float4* o = (float4*)(g_erbf + (size_t)e * 24);
    #pragma unroll
    for (int q = 0; q < 6; q++) o[q] = ((float4*)buf)[q];
}

// ---------------- gather accumulation (CSR, prefetched, no fp atomics) ----------------
__global__ void __launch_bounds__(128) k_gather(const int* __restrict__ src,
                                                const float* __restrict__ bw,
                                                const float* __restrict__ emb,
                                                const int* __restrict__ z) {
    int t = threadIdx.x;
    float w0[20], w2[20];
    #pragma unroll
    for (int k = 0; k < 20; k++) {
        w0[k] = g_WwT[k * TF + t];
        w2[k] = g_WwT[k * TF + 256 + t];
    }
    float b0 = bw[t], b2 = bw[256 + t];
    int nbase = blockIdx.x * 32;
    for (int ii = 0; ii < 32; ii++) {
        int n = nbase + ii;
        if (n >= NN) break;
        int e0 = g_off[n], e1 = g_off[n + 1];
        float accs = 0.f, av0 = 0.f, av1 = 0.f, av2 = 0.f;
        int eC = 0, sC = 0;
        if (e0 < e1) { eC = g_eid[e0]; sC = __ldg(&src[eC]); }
        for (int idx = e0; idx < e1; idx++) {
            const float4* eb = (const float4*)(g_erbf + (size_t)eC * 24);
            float4 q0 = eb[0], q1 = eb[1], q2 = eb[2], q3 = eb[3], q4 = eb[4], q5 = eb[5];
            float p0 = g_phi[(size_t)sC * TF + t];
            float p2 = g_phi[(size_t)sC * TF + 256 + t];
            if (idx + 1 < e1) { eC = g_eid[idx + 1]; sC = __ldg(&src[eC]); }
            float r[20];
            r[0] = q0.w;
            r[1] = q1.x; r[2] = q1.y; r[3] = q1.z; r[4] = q1.w;
            r[5] = q2.x; r[6] = q2.y; r[7] = q2.z; r[8] = q2.w;
            r[9] = q3.x; r[10] = q3.y; r[11] = q3.z; r[12] = q3.w;
            r[13] = q4.x; r[14] = q4.y; r[15] = q4.z; r[16] = q4.w;
            r[17] = q5.x; r[18] = q5.y; r[19] = q5.z;
            float wf0 = b0, wf2 = b2;
            #pragma unroll
            for (int k = 0; k < 20; k++) {
                wf0 = fmaf(r[k], w0[k], wf0);
                wf2 = fmaf(r[k], w2[k], wf2);
            }
            float m2 = p2 * wf2;
            accs = fmaf(p0, wf0, accs);
            av0 = fmaf(m2, q0.x, av0);
            av1 = fmaf(m2, q0.y, av1);
            av2 = fmaf(m2, q0.z, av2);
        }
        int zn = z[n];
        g_h[n * 256 + t] = emb[(size_t)zn * 128 + t] + accs;
        g_v[(n * 3 + 0) * FF + t] = av0;
        g_v[(n * 3 + 1) * FF + t] = av1;
        g_v[(n * 3 + 2) * FF + t] = av2;
    }
}

// ---------------- fused 2-layer MLP (silu hidden), 64 rows/block, FFMA2 ----------------
// EMBED=1: A row = emb[z[row]] (KIN=128).  EMBED=0: A = in (row-major, KIN).
template <int KIN, int EMBED>
__global__ void __launch_bounds__(256) k_mlp(const float* __restrict__ in,
                                             const int* __restrict__ z,
                                             const float* __restrict__ W1,
                                             const float* __restrict__ b1,
                                             const float* __restrict__ W2,
                                             const float* __restrict__ b2,
                                             float* __restrict__ out) {
    __shared__ float As[16][64];
    __shared__ float Ws[16][128];
    __shared__ float Hs[64][132];

    int tid = threadIdx.x;
    int cg = tid & 15, rg = tid >> 4;
    int rowbase = blockIdx.x * 64;
    int lr = tid >> 2, lk4 = (tid & 3) * 4;   // A-tile loader coords
    int lo = tid >> 1, lk8 = (tid & 1) * 8;   // W-tile loader coords

    // hoisted A row pointer (embedding fused)
    int arow_i = rowbase + lr;
    bool rok = arow_i < NN;
    const float* arow;
    if (EMBED) {
        int zr = rok ? z[arow_i] : 0;
        arow = in + (size_t)zr * KIN;
    } else {
        arow = in + (size_t)arow_i * KIN;
    }

    ull acc2[4][4];
    #pragma unroll
    for (int i = 0; i < 4; i++)
        #pragma unroll
        for (int jp = 0; jp < 4; jp++) acc2[i][jp] = 0ull;

    // ---- layer 1 ----
    for (int kb = 0; kb < KIN; kb += 16) {
        {
            float4 v = make_float4(0.f, 0.f, 0.f, 0.f);
            if (rok) v = *(const float4*)&arow[kb + lk4];
            As[lk4 + 0][lr] = v.x; As[lk4 + 1][lr] = v.y;
            As[lk4 + 2][lr] = v.z; As[lk4 + 3][lr] = v.w;
        }
        {
            const float* wr = W1 + (size_t)lo * KIN + kb + lk8;
            float4 a = *(const float4*)wr;
            float4 b = *(const float4*)(wr + 4);
            Ws[lk8 + 0][lo] = a.x; Ws[lk8 + 1][lo] = a.y;
            Ws[lk8 + 2][lo] = a.z; Ws[lk8 + 3][lo] = a.w;
            Ws[lk8 + 4][lo] = b.x; Ws[lk8 + 5][lo] = b.y;
            Ws[lk8 + 6][lo] = b.z; Ws[lk8 + 7][lo] = b.w;
        }
        __syncthreads();
        #pragma unroll
        for (int kk = 0; kk < 16; kk++) {
            float4 a4 = *(const float4*)&As[kk][rg * 4];
            ulonglong2 wA = *(const ulonglong2*)&Ws[kk][cg * 4];
            ulonglong2 wB = *(const ulonglong2*)&Ws[kk][64 + cg * 4];
            ull w2[4] = {wA.x, wA.y, wB.x, wB.y};
            float av[4] = {a4.x, a4.y, a4.z, a4.w};
            #pragma unroll
            for (int i = 0; i < 4; i++) {
                ull a2 = pk2(av[i], av[i]);
                #pragma unroll
                for (int jp = 0; jp < 4; jp++)
                    acc2[i][jp] = ffma2(a2, w2[jp], acc2[i][jp]);
            }
        }
        __syncthreads();
    }
    // silu + bias -> Hs  (layout [row][k], padded)
    {
        float4 u0 = *(const float4*)&b1[cg * 4];
        float4 u1 = *(const float4*)&b1[64 + cg * 4];
        float bb[8] = {u0.x, u0.y, u0.z, u0.w, u1.x, u1.y, u1.z, u1.w};
        #pragma unroll
        for (int i = 0; i < 4; i++) {
            float h[8];
            #pragma unroll
            for (int jp = 0; jp < 4; jp++) {
                float x0, x1;
                upk2(acc2[i][jp], x0, x1);
                x0 += bb[2 * jp]; x1 += bb[2 * jp + 1];
                h[2 * jp] = x0 / (1.0f + expf(-x0));
                h[2 * jp + 1] = x1 / (1.0f + expf(-x1));
            }
            *(float4*)&Hs[rg * 4 + i][cg * 4] = make_float4(h[0], h[1], h[2], h[3]);
            *(float4*)&Hs[rg * 4 + i][64 + cg * 4] = make_float4(h[4], h[5], h[6], h[7]);
        }
    }
    __syncthreads();

    // ---- layer 2: 3 output blocks of 128 ----
    for (int ob = 0; ob < 3; ob++) {
        #pragma unroll
        for (int i = 0; i < 4; i++)
            #pragma unroll
            for (int jp = 0; jp < 4; jp++) acc2[i][jp] = 0ull;
        for (int kb = 0; kb < 128; kb += 16) {
            {
                const float* wr = W2 + (size_t)(ob * 128 + lo) * 128 + kb + lk8;
                float4 a = *(const float4*)wr;
                float4 b = *(const float4*)(wr + 4);
                Ws[lk8 + 0][lo] = a.x; Ws[lk8 + 1][lo] = a.y;
                Ws[lk8 + 2][lo] = a.z; Ws[lk8 + 3][lo] = a.w;
                Ws[lk8 + 4][lo] = b.x; Ws[lk8 + 5][lo] = b.y;
                Ws[lk8 + 6][lo] = b.z; Ws[lk8 + 7][lo] = b.w;
            }
            __syncthreads();
            #pragma unroll
            for (int kk = 0; kk < 16; kk++) {
                ulonglong2 wA = *(const ulonglong2*)&Ws[kk][cg * 4];
                ulonglong2 wB = *(const ulonglong2*)&Ws[kk][64 + cg * 4];
                ull w2[4] = {wA.x, wA.y, wB.x, wB.y};
                #pragma unroll
                for (int i = 0; i < 4; i++) {
                    float av = Hs[rg * 4 + i][kb + kk];
                    ull a2 = pk2(av, av);
                    #pragma unroll
                    for (int jp = 0; jp < 4; jp++)
                        acc2[i][jp] = ffma2(a2, w2[jp], acc2[i][jp]);
                }
            }
            __syncthreads();
        }
        float4 u0 = *(const float4*)&b2[ob * 128 + cg * 4];
        float4 u1 = *(const float4*)&b2[ob * 128 + 64 + cg * 4];
        float bb[8] = {u0.x, u0.y, u0.z, u0.w, u1.x, u1.y, u1.z, u1.w};
        #pragma unroll
        for (int i = 0; i < 4; i++) {
            int row = rowbase + rg * 4 + i;
            if (row < NN) {
                float o[8];
                #pragma unroll
                for (int jp = 0; jp < 4; jp++) {
                    float x0, x1;
                    upk2(acc2[i][jp], x0, x1);
                    o[2 * jp] = x0 + bb[2 * jp];
                    o[2 * jp + 1] = x1 + bb[2 * jp + 1];
                }
                *(float4*)&out[(size_t)row * TF + ob * 128 + cg * 4] =
                    make_float4(o[0], o[1], o[2], o[3]);
                *(float4*)&out[(size_t)row * TF + ob * 128 + 64 + cg * 4] =
                    make_float4(o[4], o[5], o[6], o[7]);
            }
        }
    }
}

// ---------------- dual GEMM: U = v@Wu^T+bu, V = v@Wv^T+bv, M = 3N rows, FFMA2 ----------------
__global__ void __launch_bounds__(256) k_uv(const float* __restrict__ Wu,
                                            const float* __restrict__ bu,
                                            const float* __restrict__ Wv,
                                            const float* __restrict__ bv) {
    const int M = NN * 3;
    __shared__ float As[16][64];
    __shared__ float WsU[16][128];
    __shared__ float WsV[16][128];

    int tid = threadIdx.x;
    int cg = tid & 15, rg = tid >> 4;
    int rowbase = blockIdx.x * 64;
    int lr = tid >> 2, lk4 = (tid & 3) * 4;
    int lo = tid >> 1, lk8 = (tid & 1) * 8;

    ull accU2[4][4], accV2[4][4];
    #pragma unroll
    for (int i = 0; i < 4; i++)
        #pragma unroll
        for (int jp = 0; jp < 4; jp++) { accU2[i][jp] = 0ull; accV2[i][jp] = 0ull; }

    for (int kb = 0; kb < 128; kb += 16) {
        {
            int row = rowbase + lr;
            float4 v = make_float4(0.f, 0.f, 0.f, 0.f);
            if (row < M) v = *(const float4*)&g_v[(size_t)row * 128 + kb + lk4];
            As[lk4 + 0][lr] = v.x; As[lk4 + 1][lr] = v.y;
            As[lk4 + 2][lr] = v.z; As[lk4 + 3][lr] = v.w;
        }
        {
            const float* wr = Wu + (size_t)lo * 128 + kb + lk8;
            float4 a = *(const float4*)wr;
            float4 b = *(const float4*)(wr + 4);
            WsU[lk8 + 0][lo] = a.x; WsU[lk8 + 1][lo] = a.y;
            WsU[lk8 + 2][lo] = a.z; WsU[lk8 + 3][lo] = a.w;
            WsU[lk8 + 4][lo] = b.x; WsU[lk8 + 5][lo] = b.y;
            WsU[lk8 + 6][lo] = b.z; WsU[lk8 + 7][lo] = b.w;
        }
        {
            const float* wr = Wv + (size_t)lo * 128 + kb + lk8;
            float4 a = *(const float4*)wr;
            float4 b = *(const float4*)(wr + 4);
            WsV[lk8 + 0][lo] = a.x; WsV[lk8 + 1][lo] = a.y;
            WsV[lk8 + 2][lo] = a.z; WsV[lk8 + 3][lo] = a.w;
            WsV[lk8 + 4][lo] = b.x; WsV[lk8 + 5][lo] = b.y;
            WsV[lk8 + 6][lo] = b.z; WsV[lk8 + 7][lo] = b.w;
        }
        __syncthreads();
        #pragma unroll
        for (int kk = 0; kk < 16; kk++) {
            float4 a4 = *(const float4*)&As[kk][rg * 4];
            float av[4] = {a4.x, a4.y, a4.z, a4.w};
            ulonglong2 uA = *(const ulonglong2*)&WsU[kk][cg * 4];
            ulonglong2 uB = *(const ulonglong2*)&WsU[kk][64 + cg * 4];
            ulonglong2 vA = *(const ulonglong2*)&WsV[kk][cg * 4];
            ulonglong2 vB = *(const ulonglong2*)&WsV[kk][64 + cg * 4];
            ull wu[4] = {uA.x, uA.y, uB.x, uB.y};
            ull wv[4] = {vA.x, vA.y, vB.x, vB.y};
            #pragma unroll
            for (int i = 0; i < 4; i++) {
                ull a2 = pk2(av[i], av[i]);
                #pragma unroll
                for (int jp = 0; jp < 4; jp++) {
                    accU2[i][jp] = ffma2(a2, wu[jp], accU2[i][jp]);
                    accV2[i][jp] = ffma2(a2, wv[jp], accV2[i][jp]);
                }
            }
        }
        __syncthreads();
    }
    float4 bu0 = *(const float4*)&bu[cg * 4];
    float4 bu1 = *(const float4*)&bu[64 + cg * 4];
    float4 bv0 = *(const float4*)&bv[cg * 4];
    float4 bv1 = *(const float4*)&bv[64 + cg * 4];
    float bbu[8] = {bu0.x, bu0.y, bu0.z, bu0.w, bu1.x, bu1.y, bu1.z, bu1.w};
    float bbv[8] = {bv0.x, bv0.y, bv0.z, bv0.w, bv1.x, bv1.y, bv1.z, bv1.w};
    #pragma unroll
    for (int i = 0; i < 4; i++) {
        int row = rowbase + rg * 4 + i;
        if (row < M) {
            float ou[8], ov[8];
            #pragma unroll
            for (int jp = 0; jp < 4; jp++) {
                float x0, x1;
                upk2(accU2[i][jp], x0, x1);
                ou[2 * jp] = x0 + bbu[2 * jp];
                ou[2 * jp + 1] = x1 + bbu[2 * jp + 1];
                upk2(accV2[i][jp], x0, x1);
                ov[2 * jp] = x0 + bbv[2 * jp];
                ov[2 * jp + 1] = x1 + bbv[2 * jp + 1];
            }
            *(float4*)&g_U[(size_t)row * 128 + cg * 4] =
                make_float4(ou[0], ou[1], ou[2], ou[3]);
            *(float4*)&g_U[(size_t)row * 128 + 64 + cg * 4] =
                make_float4(ou[4], ou[5], ou[6], ou[7]);
            *(float4*)&g_V[(size_t)row * 128 + cg * 4] =
                make_float4(ov[0], ov[1], ov[2], ov[3]);
            *(float4*)&g_V[(size_t)row * 128 + 64 + cg * 4] =
                make_float4(ov[4], ov[5], ov[6], ov[7]);
        }
    }
}

__global__ void k_vn() {
    int i = blockIdx.x * 256 + threadIdx.x;      // exactly NN*FF threads
    int n = i >> 7, f = i & 127;
    float x = g_V[(n * 3 + 0) * FF + f];
    float y = g_V[(n * 3 + 1) * FF + f];
    float z = g_V[(n * 3 + 2) * FF + f];
    g_h[n * 256 + 128 + f] = sqrtf(x * x + y * y + z * z);
}

__global__ void k_final(float* __restrict__ out) {
    int i = blockIdx.x * 256 + threadIdx.x;      // exactly NN*FF threads
    int n = i >> 7, f = i & 127;
    const float* ga = g_a + (size_t)n * TF;
    float a1 = ga[f], a2 = ga[128 + f], a3 = ga[256 + f];
    float dot = 0.f;
    float vo[3];
    #pragma unroll
    for (int c = 0; c < 3; c++) {
        int idx = (n * 3 + c) * FF + f;
        float Uc = g_U[idx], Vc = g_V[idx];
        dot = fmaf(Uc, Vc, dot);
        vo[c] = g_v[idx] + Uc * a1;
    }
    out[i] = g_h[n * 256 + f] + a2 + dot * a3;
    float* vp = out + (size_t)NN * FF + (size_t)i * 3;
    vp[0] = vo[0]; vp[1] = vo[1]; vp[2] = vo[2];
}

// ---------------- launch ----------------
extern "C" void kernel_launch(void* const* d_in, const int* in_sizes, int n_in,
                              void* d_out, int out_size) {
    const float* pos = (const float*)d_in[0];
    const float* emb = (const float*)d_in[1];
    const float* Wp1 = (const float*)d_in[2];
    const float* bp1 = (const float*)d_in[3];
    const float* Wp2 = (const float*)d_in[4];
    const float* bp2 = (const float*)d_in[5];
    const float* Ww  = (const float*)d_in[6];
    const float* bw  = (const float*)d_in[7];
    const float* Wu  = (const float*)d_in[8];
    const float* bu  = (const float*)d_in[9];
    const float* Wv  = (const float*)d_in[10];
    const float* bv  = (const float*)d_in[11];
    const float* Wu1 = (const float*)d_in[12];
    const float* bu1 = (const float*)d_in[13];
    const float* Wu2 = (const float*)d_in[14];
    const float* bu2 = (const float*)d_in[15];
    const int* z   = (const int*)d_in[16];
    const int* src = (const int*)d_in[17];
    const int* dst = (const int*)d_in[18];
    float* out = (float*)d_out;

    float *p_phi, *p_h, *p_a;
    cudaGetSymbolAddress((void**)&p_phi, g_phi);
    cudaGetSymbolAddress((void**)&p_h, g_h);
    cudaGetSymbolAddress((void**)&p_a, g_a);

    const int gridNF = (NN * FF) / 256;          // 25000
    const int gridE  = (EE + 255) / 256;         // 1563
    const int gridN  = (NN + 255) / 256;         // 196
    const int gridM64  = (NN + 63) / 64;         // 782
    const int gridM64x3 = (NN * 3 + 63) / 64;    // 2344
    const int gridGather = (NN + 31) / 32;       // 1563

    // launch order chosen so the 4th launch (profiled by ncu -s) is the phi-MLP GEMM
    k_zero_cnt<<<gridN, 256>>>();
    k_count<<<gridE, 256>>>(dst);
    k_scan<<<1, 1024>>>();
    k_mlp<128, 1><<<gridM64, 256>>>(emb, z, Wp1, bp1, Wp2, bp2, p_phi);   // <- profiled
    k_scatter<<<gridE, 256>>>(dst);
    k_edge<<<gridE, 256>>>(pos, src, dst);
    k_wwt<<<(TF * 20 + 255) / 256, 256>>>(Ww);

    k_gather<<<gridGather, 128>>>(src, bw, emb, z);

    k_uv<<<gridM64x3, 256>>>(Wu, bu, Wv, bv);
    k_vn<<<gridNF, 256>>>();
    k_mlp<256, 0><<<gridM64, 256>>>(p_h, z, Wu1, bu1, Wu2, bu2, p_a);
    k_final<<<gridNF, 256>>>(out);
}